// round 2
// baseline (speedup 1.0000x reference)
#include <cuda_runtime.h>

// Problem constants
#define B_  2
#define S_  2048
#define DM  768
#define H_  12
#define DK  64

// Scratch (allocation-free rule: device globals)
__device__ float g_Q[B_ * S_ * DM];
__device__ float g_K[B_ * S_ * DM];
__device__ float g_V[B_ * S_ * DM];
__device__ float g_X[B_ * S_ * DM];

// ---------------------------------------------------------------------------
// GEMM: C[M,N] = A[M,K] @ W[N,K]^T + bias[N]
// (torch Linear layout: W row-major [out_features, in_features])
// 128x128 tile, BK=8, 256 threads, 8x8 microtile.
// M % 128 == 0, N % 128 == 0, K % 8 == 0 (holds: 4096, 768, 768).
// ---------------------------------------------------------------------------
__global__ __launch_bounds__(256) void gemm_nt_bias(
    const float* __restrict__ A, const float* __restrict__ W,
    const float* __restrict__ bias, float* __restrict__ C,
    int M, int N, int K)
{
    __shared__ float As[8][128];
    __shared__ float Ws[8][128];

    const int t  = threadIdx.x;
    const int tx = t & 15;        // 0..15 -> N microtile
    const int ty = t >> 4;        // 0..15 -> M microtile
    const int bm = blockIdx.y * 128;
    const int bn = blockIdx.x * 128;

    const int lrow = t >> 1;        // 0..127
    const int lk   = (t & 1) * 4;   // 0 or 4

    float acc[8][8];
#pragma unroll
    for (int i = 0; i < 8; i++)
#pragma unroll
        for (int j = 0; j < 8; j++) acc[i][j] = 0.f;

    const float* Aptr = A + (size_t)(bm + lrow) * K + lk;
    const float* Wptr = W + (size_t)(bn + lrow) * K + lk;

    for (int kt = 0; kt < K; kt += 8) {
        float4 av = *(const float4*)(Aptr + kt);
        float4 wv = *(const float4*)(Wptr + kt);
        As[lk + 0][lrow] = av.x;
        As[lk + 1][lrow] = av.y;
        As[lk + 2][lrow] = av.z;
        As[lk + 3][lrow] = av.w;
        Ws[lk + 0][lrow] = wv.x;
        Ws[lk + 1][lrow] = wv.y;
        Ws[lk + 2][lrow] = wv.z;
        Ws[lk + 3][lrow] = wv.w;
        __syncthreads();

#pragma unroll
        for (int k = 0; k < 8; k++) {
            float a[8], b[8];
            *(float4*)&a[0] = *(const float4*)&As[k][ty * 8 + 0];
            *(float4*)&a[4] = *(const float4*)&As[k][ty * 8 + 4];
            *(float4*)&b[0] = *(const float4*)&Ws[k][tx * 8 + 0];
            *(float4*)&b[4] = *(const float4*)&Ws[k][tx * 8 + 4];
#pragma unroll
            for (int i = 0; i < 8; i++)
#pragma unroll
                for (int j = 0; j < 8; j++)
                    acc[i][j] = fmaf(a[i], b[j], acc[i][j]);
        }
        __syncthreads();
    }

    // Epilogue: add bias, write.
    float bv[8];
#pragma unroll
    for (int j = 0; j < 8; j++) bv[j] = bias[bn + tx * 8 + j];

#pragma unroll
    for (int i = 0; i < 8; i++) {
        float* crow = C + (size_t)(bm + ty * 8 + i) * N + bn + tx * 8;
        float4 o0 = { acc[i][0] + bv[0], acc[i][1] + bv[1],
                      acc[i][2] + bv[2], acc[i][3] + bv[3] };
        float4 o1 = { acc[i][4] + bv[4], acc[i][5] + bv[5],
                      acc[i][6] + bv[6], acc[i][7] + bv[7] };
        *(float4*)(crow + 0) = o0;
        *(float4*)(crow + 4) = o1;
    }
}

// ---------------------------------------------------------------------------
// Causal flash attention, fp32.
// One thread per query row; 128 rows per block; K/V staged in smem in chunks
// of 64 keys. All smem reads during compute are warp-uniform (broadcast).
// Q/K/V layouts: [B, S, DM] with head h at columns [h*64, h*64+64).
// Writes X in the same [B, S, DM] layout (== transpose-back in reference).
// ---------------------------------------------------------------------------
__global__ __launch_bounds__(128) void attn_kernel(
    const float* __restrict__ Q, const float* __restrict__ K,
    const float* __restrict__ V, float* __restrict__ X)
{
    __shared__ float Ks[64 * 64];
    __shared__ float Vs[64 * 64];

    const int tid = threadIdx.x;
    const int h   = blockIdx.y;
    const int b   = blockIdx.z;
    const int qi  = blockIdx.x * 128 + tid;   // query row (always < S_)

    const float* qptr = Q + ((size_t)(b * S_ + qi)) * DM + h * DK;
    float q[DK];
#pragma unroll
    for (int d = 0; d < DK; d += 4)
        *(float4*)&q[d] = *(const float4*)(qptr + d);

    float o[DK];
#pragma unroll
    for (int d = 0; d < DK; d++) o[d] = 0.f;
    float m = -1e30f, l = 0.f;

    const int kmax = blockIdx.x * 128 + 128;  // causal bound for this block

    for (int c0 = 0; c0 < kmax; c0 += 64) {
        const float* kbase = K + ((size_t)(b * S_ + c0)) * DM + h * DK;
        const float* vbase = V + ((size_t)(b * S_ + c0)) * DM + h * DK;
        // 64 rows x 16 float4 = 1024 float4; 8 per thread, coalesced 16/row.
#pragma unroll
        for (int i = 0; i < 8; i++) {
            int idx = tid + i * 128;
            int j   = idx >> 4;
            int cc  = (idx & 15) << 2;
            *(float4*)&Ks[j * 64 + cc] = *(const float4*)(kbase + (size_t)j * DM + cc);
            *(float4*)&Vs[j * 64 + cc] = *(const float4*)(vbase + (size_t)j * DM + cc);
        }
        __syncthreads();

        int jend = qi - c0 + 1;
        if (jend > 64) jend = 64;

        for (int j = 0; j < jend; j++) {
            const float4* k4 = (const float4*)&Ks[j * 64];
            float s = 0.f;
#pragma unroll
            for (int dd = 0; dd < 16; dd++) {
                float4 kv = k4[dd];
                s = fmaf(q[dd * 4 + 0], kv.x, s);
                s = fmaf(q[dd * 4 + 1], kv.y, s);
                s = fmaf(q[dd * 4 + 2], kv.z, s);
                s = fmaf(q[dd * 4 + 3], kv.w, s);
            }
            s *= 0.125f;  // 1/sqrt(64)

            const float4* v4 = (const float4*)&Vs[j * 64];
            if (s > m) {
                float c = __expf(m - s);   // exp(-1e30-s) == 0 on first hit
                m = s;
                l = l * c + 1.f;           // p = exp(s - m_new) = 1
#pragma unroll
                for (int dd = 0; dd < 16; dd++) {
                    float4 vv = v4[dd];
                    o[dd * 4 + 0] = fmaf(o[dd * 4 + 0], c, vv.x);
                    o[dd * 4 + 1] = fmaf(o[dd * 4 + 1], c, vv.y);
                    o[dd * 4 + 2] = fmaf(o[dd * 4 + 2], c, vv.z);
                    o[dd * 4 + 3] = fmaf(o[dd * 4 + 3], c, vv.w);
                }
            } else {
                float p = __expf(s - m);
                l += p;
#pragma unroll
                for (int dd = 0; dd < 16; dd++) {
                    float4 vv = v4[dd];
                    o[dd * 4 + 0] = fmaf(p, vv.x, o[dd * 4 + 0]);
                    o[dd * 4 + 1] = fmaf(p, vv.y, o[dd * 4 + 1]);
                    o[dd * 4 + 2] = fmaf(p, vv.z, o[dd * 4 + 2]);
                    o[dd * 4 + 3] = fmaf(p, vv.w, o[dd * 4 + 3]);
                }
            }
        }
        __syncthreads();
    }

    const float inv = 1.f / l;
    float* xptr = g_X + ((size_t)(b * S_ + qi)) * DM + h * DK;
    (void)X;
#pragma unroll
    for (int d = 0; d < DK; d += 4) {
        float4 ov = { o[d + 0] * inv, o[d + 1] * inv,
                      o[d + 2] * inv, o[d + 3] * inv };
        *(float4*)(xptr + d) = ov;
    }
}

// ---------------------------------------------------------------------------
// Launch
// Inputs (metadata order): 0:q 1:k 2:v 3:mask 4:wq 5:bq 6:wk 7:bk 8:wv 9:bv
//                          10:wo 11:bo
// ---------------------------------------------------------------------------
extern "C" void kernel_launch(void* const* d_in, const int* in_sizes, int n_in,
                              void* d_out, int out_size)
{
    const float* q  = (const float*)d_in[0];
    const float* k  = (const float*)d_in[1];
    const float* v  = (const float*)d_in[2];
    const float* wq = (const float*)d_in[4];
    const float* bq = (const float*)d_in[5];
    const float* wk = (const float*)d_in[6];
    const float* bk = (const float*)d_in[7];
    const float* wv = (const float*)d_in[8];
    const float* bv = (const float*)d_in[9];
    const float* wo = (const float*)d_in[10];
    const float* bo = (const float*)d_in[11];
    float* out = (float*)d_out;

    float *gQ, *gK, *gV, *gX;
    cudaGetSymbolAddress((void**)&gQ, g_Q);
    cudaGetSymbolAddress((void**)&gK, g_K);
    cudaGetSymbolAddress((void**)&gV, g_V);
    cudaGetSymbolAddress((void**)&gX, g_X);

    const int M = B_ * S_;  // 4096
    dim3 ggrid(DM / 128, M / 128);   // (6, 32)
    dim3 gblk(256);

    gemm_nt_bias<<<ggrid, gblk>>>(q, wq, bq, gQ, M, DM, DM);
    gemm_nt_bias<<<ggrid, gblk>>>(k, wk, bk, gK, M, DM, DM);
    gemm_nt_bias<<<ggrid, gblk>>>(v, wv, bv, gV, M, DM, DM);

    dim3 agrid(S_ / 128, H_, B_);    // (16, 12, 2)
    attn_kernel<<<agrid, 128>>>(gQ, gK, gV, gX);

    gemm_nt_bias<<<ggrid, gblk>>>(gX, wo, bo, out, M, DM, DM);
}